// round 1
// baseline (speedup 1.0000x reference)
#include <cuda_runtime.h>
#include <math_constants.h>
#include <cstdint>

// Problem constants
#define Bc   4
#define Sc   1024
#define Hc   2048
#define NHc  16
#define KVHc 4
#define HDc  128
#define Ic   8192
#define Mc   (Bc*Sc)   // 4096 tokens

// ---------------------------------------------------------------------------
// Scratch (device globals: allocation-free rule)
// ---------------------------------------------------------------------------
__device__ float g_ln  [(size_t)Mc * Hc];            // rmsnorm output (reused)
__device__ float g_q   [(size_t)Mc * (NHc  * HDc)];  // (B,S,NH,HD)
__device__ float g_k   [(size_t)Mc * (KVHc * HDc)];  // (B,S,KVH,HD)
__device__ float g_v   [(size_t)Mc * (KVHc * HDc)];
__device__ float g_attn[(size_t)Mc * (NHc  * HDc)];  // attention output (B,S,NH*HD)
__device__ float g_h1  [(size_t)Mc * Hc];            // residual after attention
__device__ float g_gu  [(size_t)Mc * (2 * Ic)];      // gate_up raw
__device__ float g_act [(size_t)Mc * Ic];            // silu(gate)*up

// ---------------------------------------------------------------------------
// RMSNorm: one block per token row (H = 2048)
// ---------------------------------------------------------------------------
__global__ __launch_bounds__(256)
void rmsnorm_kernel(const float* __restrict__ x, const float* __restrict__ w,
                    float* __restrict__ y)
{
    __shared__ float red[8];
    const int row = blockIdx.x;
    const int tid = threadIdx.x;
    const float4* xr = (const float4*)(x + (size_t)row * Hc);
    const float4* w4 = (const float4*)w;
    float4* yr = (float4*)(y + (size_t)row * Hc);

    float4 v0 = xr[tid], v1 = xr[tid + 256];
    float ss = v0.x*v0.x + v0.y*v0.y + v0.z*v0.z + v0.w*v0.w
             + v1.x*v1.x + v1.y*v1.y + v1.z*v1.z + v1.w*v1.w;
    #pragma unroll
    for (int o = 16; o; o >>= 1) ss += __shfl_xor_sync(0xffffffffu, ss, o);
    if ((tid & 31) == 0) red[tid >> 5] = ss;
    __syncthreads();
    if (tid < 8) {
        float t = red[tid];
        #pragma unroll
        for (int o = 4; o; o >>= 1) t += __shfl_xor_sync(0xffu, t, o);
        if (tid == 0) red[0] = t;
    }
    __syncthreads();
    const float inv = rsqrtf(red[0] * (1.0f / (float)Hc) + 1e-6f);

    float4 wv0 = w4[tid], wv1 = w4[tid + 256];
    float4 o0, o1;
    o0.x = v0.x*inv*wv0.x; o0.y = v0.y*inv*wv0.y; o0.z = v0.z*inv*wv0.z; o0.w = v0.w*inv*wv0.w;
    o1.x = v1.x*inv*wv1.x; o1.y = v1.y*inv*wv1.y; o1.z = v1.z*inv*wv1.z; o1.w = v1.w*inv*wv1.w;
    yr[tid] = o0; yr[tid + 256] = o1;
}

// ---------------------------------------------------------------------------
// NT GEMM: C[M,N] = A[M,K] * W[N,K]^T  (+ optional residual R)
// BM=BN=128, BK=16, 256 threads, 8x8 per-thread tile.
// M,N multiples of 128; K multiple of 16 (all shapes here qualify).
// ---------------------------------------------------------------------------
template<bool RESID>
__global__ __launch_bounds__(256)
void gemm_nt_kernel(const float* __restrict__ A, const float* __restrict__ W,
                    const float* __restrict__ R, float* __restrict__ C,
                    int N, int K)
{
    __shared__ float As[16][128];
    __shared__ float Ws[16][128];
    const int tid = threadIdx.x;
    const int tx = tid & 15, ty = tid >> 4;
    const size_t bm = blockIdx.y, bn = blockIdx.x;
    const float* Ab = A + bm * 128 * (size_t)K;
    const float* Wb = W + bn * 128 * (size_t)K;

    float acc[8][8];
    #pragma unroll
    for (int i = 0; i < 8; ++i)
        #pragma unroll
        for (int j = 0; j < 8; ++j) acc[i][j] = 0.f;

    for (int k0 = 0; k0 < K; k0 += 16) {
        #pragma unroll
        for (int it = 0; it < 2; ++it) {
            int l   = tid * 2 + it;       // 0..511 float4 slots
            int row = l >> 2;             // 0..127
            int kq  = (l & 3) << 2;       // 0,4,8,12
            float4 a  = *(const float4*)(Ab + (size_t)row * K + k0 + kq);
            float4 wv = *(const float4*)(Wb + (size_t)row * K + k0 + kq);
            As[kq+0][row] = a.x;  As[kq+1][row] = a.y;  As[kq+2][row] = a.z;  As[kq+3][row] = a.w;
            Ws[kq+0][row] = wv.x; Ws[kq+1][row] = wv.y; Ws[kq+2][row] = wv.z; Ws[kq+3][row] = wv.w;
        }
        __syncthreads();
        #pragma unroll
        for (int k = 0; k < 16; ++k) {
            float a[8], b[8];
            *(float4*)(a)     = *(const float4*)&As[k][ty*8];
            *(float4*)(a + 4) = *(const float4*)&As[k][ty*8 + 4];
            *(float4*)(b)     = *(const float4*)&Ws[k][tx*8];
            *(float4*)(b + 4) = *(const float4*)&Ws[k][tx*8 + 4];
            #pragma unroll
            for (int i = 0; i < 8; ++i)
                #pragma unroll
                for (int j = 0; j < 8; ++j)
                    acc[i][j] = fmaf(a[i], b[j], acc[i][j]);
        }
        __syncthreads();
    }

    #pragma unroll
    for (int i = 0; i < 8; ++i) {
        size_t m   = bm * 128 + ty * 8 + i;
        size_t off = m * (size_t)N + bn * 128 + tx * 8;
        float4 o0 = make_float4(acc[i][0], acc[i][1], acc[i][2], acc[i][3]);
        float4 o1 = make_float4(acc[i][4], acc[i][5], acc[i][6], acc[i][7]);
        if (RESID) {
            float4 r0 = *(const float4*)(R + off);
            float4 r1 = *(const float4*)(R + off + 4);
            o0.x += r0.x; o0.y += r0.y; o0.z += r0.z; o0.w += r0.w;
            o1.x += r1.x; o1.y += r1.y; o1.z += r1.z; o1.w += r1.w;
        }
        *(float4*)(C + off)     = o0;
        *(float4*)(C + off + 4) = o1;
    }
}

// ---------------------------------------------------------------------------
// RoPE (in-place): x layout (B,S,nheads,128); one thread per (token,head,j<64)
// ---------------------------------------------------------------------------
__global__ void rope_kernel(float* __restrict__ x, const float* __restrict__ sin_t,
                            const float* __restrict__ cos_t, int nheads, int total)
{
    int idx = blockIdx.x * blockDim.x + threadIdx.x;
    if (idx >= total) return;
    int j  = idx & 63;
    int t  = idx >> 6;               // (b*S + s)*nheads + hh
    int bs = t / nheads;
    int s  = bs & (Sc - 1);
    float c  = cos_t[s * 64 + j];
    float sn = sin_t[s * 64 + j];
    float* base = x + (size_t)t * HDc;
    float x1 = base[j], x2 = base[j + 64];
    base[j]      = x1 * c - x2 * sn;
    base[j + 64] = x2 * c + x1 * sn;
}

// ---------------------------------------------------------------------------
// Causal flash attention, fp32, GQA (4 q-heads per kv-head).
// grid (S/64, NH, B), 256 threads. BM=BN=64, HD=128.
// Dynamic smem: Q/K/V tiles (stride 132 to break stride-128 bank conflicts),
// P tile (stride 68), per-row stats.
// ---------------------------------------------------------------------------
#define FA_QS 132
#define FA_PS 68
#define FA_SMEM ((3*64*FA_QS + 64*FA_PS + 3*64) * (int)sizeof(float))

__global__ __launch_bounds__(256)
void flash_attn_kernel(const float* __restrict__ q, const float* __restrict__ k,
                       const float* __restrict__ v, float* __restrict__ o)
{
    extern __shared__ float sm[];
    float* Qs  = sm;
    float* Ks  = Qs + 64 * FA_QS;
    float* Vs  = Ks + 64 * FA_QS;
    float* Ps  = Vs + 64 * FA_QS;
    float* m_s = Ps + 64 * FA_PS;
    float* l_s = m_s + 64;
    float* c_s = l_s + 64;

    const int m0  = blockIdx.x << 6;
    const int h   = blockIdx.y;
    const int b   = blockIdx.z;
    const int kvh = h >> 2;
    const int tid = threadIdx.x;
    const int tx = tid & 15, ty = tid >> 4;
    const int r0 = ty * 4;       // 4 query rows per thread
    const int d0 = tx * 8;       // 8 output dims per thread

    // Load Q tile
    for (int l = tid; l < 64 * 32; l += 256) {
        int r = l >> 5, dq = (l & 31) << 2;
        *(float4*)&Qs[r * FA_QS + dq] =
            *(const float4*)(q + ((size_t)((b * Sc + m0 + r) * NHc + h)) * HDc + dq);
    }
    if (tid < 64) { m_s[tid] = -CUDART_INF_F; l_s[tid] = 0.f; }

    float acc[4][8];
    #pragma unroll
    for (int i = 0; i < 4; ++i)
        #pragma unroll
        for (int j = 0; j < 8; ++j) acc[i][j] = 0.f;

    const int nT = (m0 >> 6) + 1;
    const float scale = 0.08838834764831845f;  // 1/sqrt(128)

    for (int t = 0; t < nT; ++t) {
        const int n0 = t << 6;
        __syncthreads();   // previous iter's Ps/Vs reads (and Q load) done
        for (int l = tid; l < 64 * 32; l += 256) {
            int r = l >> 5, dq = (l & 31) << 2;
            size_t base = ((size_t)((b * Sc + n0 + r) * KVHc + kvh)) * HDc + dq;
            *(float4*)&Ks[r * FA_QS + dq] = *(const float4*)(k + base);
            *(float4*)&Vs[r * FA_QS + dq] = *(const float4*)(v + base);
        }
        __syncthreads();

        // Scores: rows r0..r0+3, cols tx + 16*j
        float s4[4][4];
        #pragma unroll
        for (int i = 0; i < 4; ++i)
            #pragma unroll
            for (int j = 0; j < 4; ++j) s4[i][j] = 0.f;

        #pragma unroll 8
        for (int kd = 0; kd < 128; kd += 4) {
            float4 qv[4], kv[4];
            #pragma unroll
            for (int i = 0; i < 4; ++i) qv[i] = *(const float4*)&Qs[(r0 + i) * FA_QS + kd];
            #pragma unroll
            for (int j = 0; j < 4; ++j) kv[j] = *(const float4*)&Ks[(tx + 16 * j) * FA_QS + kd];
            #pragma unroll
            for (int i = 0; i < 4; ++i)
                #pragma unroll
                for (int j = 0; j < 4; ++j) {
                    s4[i][j] = fmaf(qv[i].x, kv[j].x, s4[i][j]);
                    s4[i][j] = fmaf(qv[i].y, kv[j].y, s4[i][j]);
                    s4[i][j] = fmaf(qv[i].z, kv[j].z, s4[i][j]);
                    s4[i][j] = fmaf(qv[i].w, kv[j].w, s4[i][j]);
                }
        }

        #pragma unroll
        for (int i = 0; i < 4; ++i)
            #pragma unroll
            for (int j = 0; j < 4; ++j) {
                int gm = m0 + r0 + i;
                int gn = n0 + tx + 16 * j;
                Ps[(r0 + i) * FA_PS + tx + 16 * j] =
                    (gn <= gm) ? s4[i][j] * scale : -CUDART_INF_F;
            }
        __syncthreads();

        // Online softmax (one thread per row)
        if (tid < 64) {
            const int r = tid;
            float mold = m_s[r];
            float rowm = -CUDART_INF_F;
            #pragma unroll 8
            for (int c = 0; c < 64; ++c) rowm = fmaxf(rowm, Ps[r * FA_PS + c]);
            float mnew = fmaxf(mold, rowm);
            float corr = expf(mold - mnew);          // exp(-inf)=0 on first tile
            float sum = 0.f;
            #pragma unroll 8
            for (int c = 0; c < 64; ++c) {
                float p = expf(Ps[r * FA_PS + c] - mnew);
                Ps[r * FA_PS + c] = p;
                sum += p;
            }
            l_s[r] = l_s[r] * corr + sum;
            m_s[r] = mnew;
            c_s[r] = corr;
        }
        __syncthreads();

        // Rescale accumulators, then O += P * V
        #pragma unroll
        for (int i = 0; i < 4; ++i) {
            float cf = c_s[r0 + i];
            #pragma unroll
            for (int j = 0; j < 8; ++j) acc[i][j] *= cf;
        }
        #pragma unroll 8
        for (int n = 0; n < 64; ++n) {
            float4 v0 = *(const float4*)&Vs[n * FA_QS + d0];
            float4 v1 = *(const float4*)&Vs[n * FA_QS + d0 + 4];
            #pragma unroll
            for (int i = 0; i < 4; ++i) {
                float p = Ps[(r0 + i) * FA_PS + n];
                acc[i][0] = fmaf(p, v0.x, acc[i][0]);
                acc[i][1] = fmaf(p, v0.y, acc[i][1]);
                acc[i][2] = fmaf(p, v0.z, acc[i][2]);
                acc[i][3] = fmaf(p, v0.w, acc[i][3]);
                acc[i][4] = fmaf(p, v1.x, acc[i][4]);
                acc[i][5] = fmaf(p, v1.y, acc[i][5]);
                acc[i][6] = fmaf(p, v1.z, acc[i][6]);
                acc[i][7] = fmaf(p, v1.w, acc[i][7]);
            }
        }
    }

    // Write O (B,S,NH*HD)
    #pragma unroll
    for (int i = 0; i < 4; ++i) {
        float inv = 1.f / l_s[r0 + i];
        size_t off = ((size_t)((b * Sc + m0 + r0 + i) * NHc + h)) * HDc + d0;
        float4 o0 = make_float4(acc[i][0]*inv, acc[i][1]*inv, acc[i][2]*inv, acc[i][3]*inv);
        float4 o1 = make_float4(acc[i][4]*inv, acc[i][5]*inv, acc[i][6]*inv, acc[i][7]*inv);
        *(float4*)(o + off)     = o0;
        *(float4*)(o + off + 4) = o1;
    }
}

// ---------------------------------------------------------------------------
// SiLU(gate) * up  (gu is (M, 2I); act is (M, I)); float4 per thread
// ---------------------------------------------------------------------------
__global__ void silu_mul_kernel(const float* __restrict__ gu, float* __restrict__ act)
{
    size_t idx = (size_t)blockIdx.x * blockDim.x + threadIdx.x;  // float4 index
    size_t m  = idx / (Ic / 4);
    size_t c4 = idx % (Ic / 4);
    const float4 g = *(const float4*)(gu + m * (size_t)(2 * Ic) + c4 * 4);
    const float4 u = *(const float4*)(gu + m * (size_t)(2 * Ic) + Ic + c4 * 4);
    float4 r;
    r.x = g.x / (1.f + expf(-g.x)) * u.x;
    r.y = g.y / (1.f + expf(-g.y)) * u.y;
    r.z = g.z / (1.f + expf(-g.z)) * u.z;
    r.w = g.w / (1.f + expf(-g.w)) * u.w;
    *(float4*)(act + m * (size_t)Ic + c4 * 4) = r;
}

// ---------------------------------------------------------------------------
// Launch
// ---------------------------------------------------------------------------
extern "C" void kernel_launch(void* const* d_in, const int* in_sizes, int n_in,
                              void* d_out, int out_size)
{
    const float* h_in  = (const float*)d_in[0];
    const float* sin_t = (const float*)d_in[1];
    const float* cos_t = (const float*)d_in[2];
    const float* w_ln1 = (const float*)d_in[3];
    const float* w_q   = (const float*)d_in[4];
    const float* w_k   = (const float*)d_in[5];
    const float* w_v   = (const float*)d_in[6];
    const float* w_o   = (const float*)d_in[7];
    const float* w_ln2 = (const float*)d_in[8];
    const float* w_gu  = (const float*)d_in[9];
    const float* w_dn  = (const float*)d_in[10];
    float* out = (float*)d_out;

    float *p_ln, *p_q, *p_k, *p_v, *p_attn, *p_h1, *p_gu, *p_act;
    cudaGetSymbolAddress((void**)&p_ln,   g_ln);
    cudaGetSymbolAddress((void**)&p_q,    g_q);
    cudaGetSymbolAddress((void**)&p_k,    g_k);
    cudaGetSymbolAddress((void**)&p_v,    g_v);
    cudaGetSymbolAddress((void**)&p_attn, g_attn);
    cudaGetSymbolAddress((void**)&p_h1,   g_h1);
    cudaGetSymbolAddress((void**)&p_gu,   g_gu);
    cudaGetSymbolAddress((void**)&p_act,  g_act);

    cudaFuncSetAttribute(flash_attn_kernel,
                         cudaFuncAttributeMaxDynamicSharedMemorySize, FA_SMEM);

    // 1. attn_in = rmsnorm(h, w_ln1)
    rmsnorm_kernel<<<Mc, 256>>>(h_in, w_ln1, p_ln);

    // 2. Q/K/V projections
    gemm_nt_kernel<false><<<dim3(2048/128, Mc/128), 256>>>(p_ln, w_q, nullptr, p_q, 2048, Hc);
    gemm_nt_kernel<false><<<dim3( 512/128, Mc/128), 256>>>(p_ln, w_k, nullptr, p_k,  512, Hc);
    gemm_nt_kernel<false><<<dim3( 512/128, Mc/128), 256>>>(p_ln, w_v, nullptr, p_v,  512, Hc);

    // 3. RoPE (in place)
    rope_kernel<<<(Mc*NHc*64  + 255)/256, 256>>>(p_q, sin_t, cos_t, NHc,  Mc*NHc*64);
    rope_kernel<<<(Mc*KVHc*64 + 255)/256, 256>>>(p_k, sin_t, cos_t, KVHc, Mc*KVHc*64);

    // 4. Causal flash attention (GQA)
    flash_attn_kernel<<<dim3(Sc/64, NHc, Bc), 256, FA_SMEM>>>(p_q, p_k, p_v, p_attn);

    // 5. O projection + residual -> h1
    gemm_nt_kernel<true><<<dim3(2048/128, Mc/128), 256>>>(p_attn, w_o, h_in, p_h1, 2048, 2048);

    // 6. mlp_in = rmsnorm(h1, w_ln2)
    rmsnorm_kernel<<<Mc, 256>>>(p_h1, w_ln2, p_ln);

    // 7. gate_up GEMM
    gemm_nt_kernel<false><<<dim3(16384/128, Mc/128), 256>>>(p_ln, w_gu, nullptr, p_gu, 16384, Hc);

    // 8. silu(gate)*up
    silu_mul_kernel<<<(Mc*(Ic/4))/256, 256>>>(p_gu, p_act);

    // 9. down GEMM + residual -> out
    gemm_nt_kernel<true><<<dim3(2048/128, Mc/128), 256>>>(p_act, w_dn, p_h1, out, 2048, Ic);
}

// round 17
// speedup vs baseline: 2.4927x; 2.4927x over previous
#include <cuda_runtime.h>
#include <cuda_bf16.h>
#include <math_constants.h>
#include <cstdint>

// Problem constants
#define Bc   4
#define Sc   1024
#define Hc   2048
#define NHc  16
#define KVHc 4
#define HDc  128
#define Ic   8192
#define Mc   (Bc*Sc)   // 4096 tokens

// ---------------------------------------------------------------------------
// Scratch (device globals: allocation-free rule)
// ---------------------------------------------------------------------------
__device__ __nv_bfloat16 a_ln_h[(size_t)Mc * Hc];
__device__ __nv_bfloat16 a_ln_l[(size_t)Mc * Hc];
__device__ __nv_bfloat16 a_at_h[(size_t)Mc * Hc];
__device__ __nv_bfloat16 a_at_l[(size_t)Mc * Hc];
__device__ __nv_bfloat16 a_ac_h[(size_t)Mc * Ic];
__device__ __nv_bfloat16 a_ac_l[(size_t)Mc * Ic];

__device__ float g_q [(size_t)Mc * (NHc  * HDc)];
__device__ float g_k [(size_t)Mc * (KVHc * HDc)];
__device__ float g_v [(size_t)Mc * (KVHc * HDc)];
__device__ float g_h1[(size_t)Mc * Hc];
__device__ float g_gu[(size_t)Mc * (2 * Ic)];

__device__ __nv_bfloat16 wq_h[(size_t)2048 * 2048],  wq_l[(size_t)2048 * 2048];
__device__ __nv_bfloat16 wk_h[(size_t)512  * 2048],  wk_l[(size_t)512  * 2048];
__device__ __nv_bfloat16 wv_h[(size_t)512  * 2048],  wv_l[(size_t)512  * 2048];
__device__ __nv_bfloat16 wo_h[(size_t)2048 * 2048],  wo_l[(size_t)2048 * 2048];
__device__ __nv_bfloat16 wgu_h[(size_t)16384 * 2048], wgu_l[(size_t)16384 * 2048];
__device__ __nv_bfloat16 wdn_h[(size_t)2048 * 8192],  wdn_l[(size_t)2048 * 8192];

// ---------------------------------------------------------------------------
// PTX helpers (sm_80-baseline only: cp.async, ldmatrix, mma.sync)
// ---------------------------------------------------------------------------
__device__ __forceinline__ uint32_t smem_u32(const void* p) {
    uint32_t a;
    asm("{ .reg .u64 t; cvta.to.shared.u64 t, %1; cvt.u32.u64 %0, t; }" : "=r"(a) : "l"(p));
    return a;
}
__device__ __forceinline__ void cp16(uint32_t sadr, const void* g) {
    asm volatile("cp.async.cg.shared.global [%0], [%1], 16;" :: "r"(sadr), "l"(g));
}
__device__ __forceinline__ void cp_commit() {
    asm volatile("cp.async.commit_group;" ::: "memory");
}
__device__ __forceinline__ void cp_wait(int n) {
    if (n <= 0)      asm volatile("cp.async.wait_group 0;" ::: "memory");
    else if (n == 1) asm volatile("cp.async.wait_group 1;" ::: "memory");
    else             asm volatile("cp.async.wait_group 2;" ::: "memory");
}
__device__ __forceinline__ void ldsm4(uint32_t* r, uint32_t addr) {
    asm volatile("ldmatrix.sync.aligned.m8n8.x4.shared.b16 {%0,%1,%2,%3}, [%4];"
                 : "=r"(r[0]), "=r"(r[1]), "=r"(r[2]), "=r"(r[3]) : "r"(addr));
}
__device__ __forceinline__ void mma16816(float* d, const uint32_t* a, const uint32_t* b) {
    asm volatile(
        "mma.sync.aligned.m16n8k16.row.col.f32.bf16.bf16.f32 "
        "{%0,%1,%2,%3}, {%4,%5,%6,%7}, {%8,%9}, {%0,%1,%2,%3};"
        : "+f"(d[0]), "+f"(d[1]), "+f"(d[2]), "+f"(d[3])
        : "r"(a[0]), "r"(a[1]), "r"(a[2]), "r"(a[3]), "r"(b[0]), "r"(b[1]));
}

// hi/lo bf16 split store (4 elems)
__device__ __forceinline__ void st_hilo4(__nv_bfloat16* h, __nv_bfloat16* l,
                                         size_t off, float4 v) {
    __nv_bfloat162 h0, h1, l0, l1;
    h0.x = __float2bfloat16(v.x); h0.y = __float2bfloat16(v.y);
    h1.x = __float2bfloat16(v.z); h1.y = __float2bfloat16(v.w);
    l0.x = __float2bfloat16(v.x - __bfloat162float(h0.x));
    l0.y = __float2bfloat16(v.y - __bfloat162float(h0.y));
    l1.x = __float2bfloat16(v.z - __bfloat162float(h1.x));
    l1.y = __float2bfloat16(v.w - __bfloat162float(h1.y));
    *(__nv_bfloat162*)(h + off)     = h0;
    *(__nv_bfloat162*)(h + off + 2) = h1;
    *(__nv_bfloat162*)(l + off)     = l0;
    *(__nv_bfloat162*)(l + off + 2) = l1;
}

// ---------------------------------------------------------------------------
// fp32 -> bf16 hi/lo conversion (weights)
// ---------------------------------------------------------------------------
__global__ __launch_bounds__(256)
void cvt_hilo_kernel(const float* __restrict__ x, __nv_bfloat16* __restrict__ h,
                     __nv_bfloat16* __restrict__ l, int n4)
{
    int i = blockIdx.x * blockDim.x + threadIdx.x;
    if (i >= n4) return;
    float4 v = ((const float4*)x)[i];
    st_hilo4(h, l, (size_t)i * 4, v);
}

// ---------------------------------------------------------------------------
// RMSNorm -> bf16 hi/lo
// ---------------------------------------------------------------------------
__global__ __launch_bounds__(256)
void rmsnorm_kernel(const float* __restrict__ x, const float* __restrict__ w,
                    __nv_bfloat16* __restrict__ yh, __nv_bfloat16* __restrict__ yl)
{
    __shared__ float red[8];
    const int row = blockIdx.x;
    const int tid = threadIdx.x;
    const float4* xr = (const float4*)(x + (size_t)row * Hc);
    const float4* w4 = (const float4*)w;

    float4 v0 = xr[tid], v1 = xr[tid + 256];
    float ss = v0.x*v0.x + v0.y*v0.y + v0.z*v0.z + v0.w*v0.w
             + v1.x*v1.x + v1.y*v1.y + v1.z*v1.z + v1.w*v1.w;
    #pragma unroll
    for (int o = 16; o; o >>= 1) ss += __shfl_xor_sync(0xffffffffu, ss, o);
    if ((tid & 31) == 0) red[tid >> 5] = ss;
    __syncthreads();
    if (tid < 8) {
        float t = red[tid];
        #pragma unroll
        for (int o = 4; o; o >>= 1) t += __shfl_xor_sync(0xffu, t, o);
        if (tid == 0) red[0] = t;
    }
    __syncthreads();
    const float inv = rsqrtf(red[0] * (1.0f / (float)Hc) + 1e-6f);

    float4 wv0 = w4[tid], wv1 = w4[tid + 256];
    float4 o0, o1;
    o0.x = v0.x*inv*wv0.x; o0.y = v0.y*inv*wv0.y; o0.z = v0.z*inv*wv0.z; o0.w = v0.w*inv*wv0.w;
    o1.x = v1.x*inv*wv1.x; o1.y = v1.y*inv*wv1.y; o1.z = v1.z*inv*wv1.z; o1.w = v1.w*inv*wv1.w;
    size_t base = (size_t)row * Hc;
    st_hilo4(yh, yl, base + (size_t)tid * 4, o0);
    st_hilo4(yh, yl, base + (size_t)(tid + 256) * 4, o1);
}

// ---------------------------------------------------------------------------
// mma.sync split-bf16 GEMM: C[M,N] = A[M,K] * W[N,K]^T  (+ optional residual)
// BM=BN=128, BK=32, 4-stage cp.async pipeline, 8 warps (2x4), warp tile 64x32.
// smem rows padded to 80B so ldmatrix phases are bank-conflict-free.
// ---------------------------------------------------------------------------
#define BKg   32
#define RSg   80                   // smem row stride bytes (64B data + 16B pad)
#define TILEB (128 * RSg)          // 10240 B per tile
#define STGB  (4 * TILEB)          // Ah, Al, Wh, Wl per stage: 40960 B
#define NSTG  4
#define GEMM_SMEM (NSTG * STGB)    // 163840 B

__device__ __forceinline__ void load_stage(uint32_t st,
    const char* gAh, const char* gAl, const char* gWh, const char* gWl,
    size_t kof, size_t rowb, int tid)
{
    const char* gp[4] = {gAh, gAl, gWh, gWl};
    #pragma unroll
    for (int t = 0; t < 4; ++t) {
        uint32_t so = st + t * TILEB;
        #pragma unroll
        for (int i = 0; i < 2; ++i) {
            int slot = tid + (i << 8);      // 0..511
            int r  = slot >> 2;             // 0..127
            int cc = slot & 3;              // 0..3 (16B chunks)
            cp16(so + r * RSg + cc * 16, gp[t] + (size_t)r * rowb + kof + cc * 16);
        }
    }
    cp_commit();
}

template<bool RESID>
__global__ __launch_bounds__(256, 1)
void gemm_tc(const __nv_bfloat16* __restrict__ Ah, const __nv_bfloat16* __restrict__ Al,
             const __nv_bfloat16* __restrict__ Wh, const __nv_bfloat16* __restrict__ Wl,
             const float* __restrict__ R, float* __restrict__ C, int N, int K)
{
    extern __shared__ char sm[];
    const int tid  = threadIdx.x;
    const int wid  = tid >> 5, lane = tid & 31;
    const int bn   = blockIdx.x, bm = blockIdx.y;
    const uint32_t sb = smem_u32(sm);

    const int wm = (wid >> 2) * 64;   // warp row: 0 or 64
    const int wn = (wid & 3) * 32;    // warp col: 0,32,64,96

    const size_t rowb = (size_t)K * 2;
    const char* gAh = (const char*)(Ah + (size_t)bm * 128 * K);
    const char* gAl = (const char*)(Al + (size_t)bm * 128 * K);
    const char* gWh = (const char*)(Wh + (size_t)bn * 128 * K);
    const char* gWl = (const char*)(Wl + (size_t)bn * 128 * K);

    const int CC = K / BKg;

    #pragma unroll
    for (int c = 0; c < NSTG - 1; ++c)
        load_stage(sb + c * STGB, gAh, gAl, gWh, gWl, (size_t)c * BKg * 2, rowb, tid);

    float acc[4][4][4];
    #pragma unroll
    for (int mt = 0; mt < 4; ++mt)
        #pragma unroll
        for (int nt = 0; nt < 4; ++nt)
            #pragma unroll
            for (int j = 0; j < 4; ++j) acc[mt][nt][j] = 0.f;

    // ldmatrix lane addressing (constant per thread)
    const int aro = wm + (lane & 15);              // A row within tile
    const int bro = wn + ((lane >> 4) & 1) * 8 + (lane & 7);  // W row within tile
    const uint32_t acsel = (lane >> 4) * 16;       // A: 16B col select (k lo/hi)
    const uint32_t bcsel = ((lane >> 3) & 1) * 16; // B: 16B col select

    for (int c = 0; c < CC; ++c) {
        int rem = CC - 1 - c;
        cp_wait(rem > (NSTG - 2) ? (NSTG - 2) : rem);
        __syncthreads();

        if (c + NSTG - 1 < CC)
            load_stage(sb + ((c + NSTG - 1) % NSTG) * STGB, gAh, gAl, gWh, gWl,
                       (size_t)(c + NSTG - 1) * BKg * 2, rowb, tid);

        const uint32_t st  = sb + (c % NSTG) * STGB;
        const uint32_t sAh = st;
        const uint32_t sAl = st + TILEB;
        const uint32_t sWh = st + 2 * TILEB;
        const uint32_t sWl = st + 3 * TILEB;

        #pragma unroll
        for (int ks = 0; ks < 2; ++ks) {
            const uint32_t akc = ks * 32 + acsel;   // byte col within row
            const uint32_t bkc = ks * 32 + bcsel;

            uint32_t ah[4][4], al[4][4];
            #pragma unroll
            for (int mt = 0; mt < 4; ++mt) {
                ldsm4(ah[mt], sAh + (uint32_t)(aro + mt * 16) * RSg + akc);
                ldsm4(al[mt], sAl + (uint32_t)(aro + mt * 16) * RSg + akc);
            }
            uint32_t whf[2][4], wlf[2][4];
            #pragma unroll
            for (int p = 0; p < 2; ++p) {
                ldsm4(whf[p], sWh + (uint32_t)(bro + p * 16) * RSg + bkc);
                ldsm4(wlf[p], sWl + (uint32_t)(bro + p * 16) * RSg + bkc);
            }

            #pragma unroll
            for (int mt = 0; mt < 4; ++mt)
                #pragma unroll
                for (int nt = 0; nt < 4; ++nt) {
                    const uint32_t* bh = &whf[nt >> 1][(nt & 1) * 2];
                    const uint32_t* bl = &wlf[nt >> 1][(nt & 1) * 2];
                    mma16816(acc[mt][nt], ah[mt], bh);
                    mma16816(acc[mt][nt], ah[mt], bl);
                    mma16816(acc[mt][nt], al[mt], bh);
                }
        }
    }

    // Epilogue
    const int row0 = bm * 128 + wm + (lane >> 2);
    const int col0 = bn * 128 + wn + (lane & 3) * 2;
    #pragma unroll
    for (int mt = 0; mt < 4; ++mt)
        #pragma unroll
        for (int nt = 0; nt < 4; ++nt) {
            size_t r0 = (size_t)(row0 + mt * 16) * N + col0 + nt * 8;
            size_t r1 = r0 + (size_t)8 * N;
            float2 v0 = make_float2(acc[mt][nt][0], acc[mt][nt][1]);
            float2 v1 = make_float2(acc[mt][nt][2], acc[mt][nt][3]);
            if (RESID) {
                float2 a0 = *(const float2*)(R + r0);
                float2 a1 = *(const float2*)(R + r1);
                v0.x += a0.x; v0.y += a0.y;
                v1.x += a1.x; v1.y += a1.y;
            }
            *(float2*)(C + r0) = v0;
            *(float2*)(C + r1) = v1;
        }
}

// ---------------------------------------------------------------------------
// RoPE (in-place, fp32)
// ---------------------------------------------------------------------------
__global__ void rope_kernel(float* __restrict__ x, const float* __restrict__ sin_t,
                            const float* __restrict__ cos_t, int nheads, int total)
{
    int idx = blockIdx.x * blockDim.x + threadIdx.x;
    if (idx >= total) return;
    int j  = idx & 63;
    int t  = idx >> 6;
    int bs = t / nheads;
    int s  = bs & (Sc - 1);
    float c  = cos_t[s * 64 + j];
    float sn = sin_t[s * 64 + j];
    float* base = x + (size_t)t * HDc;
    float x1 = base[j], x2 = base[j + 64];
    base[j]      = x1 * c - x2 * sn;
    base[j + 64] = x2 * c + x1 * sn;
}

// ---------------------------------------------------------------------------
// Causal flash attention fp32 (epilogue emits bf16 hi/lo)
// ---------------------------------------------------------------------------
#define FA_QS 132
#define FA_PS 68
#define FA_SMEM ((3*64*FA_QS + 64*FA_PS + 3*64) * (int)sizeof(float))

__global__ __launch_bounds__(256)
void flash_attn_kernel(const float* __restrict__ q, const float* __restrict__ k,
                       const float* __restrict__ v,
                       __nv_bfloat16* __restrict__ oh, __nv_bfloat16* __restrict__ ol)
{
    extern __shared__ float smf[];
    float* Qs  = smf;
    float* Ks  = Qs + 64 * FA_QS;
    float* Vs  = Ks + 64 * FA_QS;
    float* Ps  = Vs + 64 * FA_QS;
    float* m_s = Ps + 64 * FA_PS;
    float* l_s = m_s + 64;
    float* c_s = l_s + 64;

    const int m0  = blockIdx.x << 6;
    const int h   = blockIdx.y;
    const int b   = blockIdx.z;
    const int kvh = h >> 2;
    const int tid = threadIdx.x;
    const int tx = tid & 15, ty = tid >> 4;
    const int r0 = ty * 4;
    const int d0 = tx * 8;

    for (int l = tid; l < 64 * 32; l += 256) {
        int r = l >> 5, dq = (l & 31) << 2;
        *(float4*)&Qs[r * FA_QS + dq] =
            *(const float4*)(q + ((size_t)((b * Sc + m0 + r) * NHc + h)) * HDc + dq);
    }
    if (tid < 64) { m_s[tid] = -CUDART_INF_F; l_s[tid] = 0.f; }

    float acc[4][8];
    #pragma unroll
    for (int i = 0; i < 4; ++i)
        #pragma unroll
        for (int j = 0; j < 8; ++j) acc[i][j] = 0.f;

    const int nT = (m0 >> 6) + 1;
    const float scale = 0.08838834764831845f;

    for (int t = 0; t < nT; ++t) {
        const int n0 = t << 6;
        __syncthreads();
        for (int l = tid; l < 64 * 32; l += 256) {
            int r = l >> 5, dq = (l & 31) << 2;
            size_t base = ((size_t)((b * Sc + n0 + r) * KVHc + kvh)) * HDc + dq;
            *(float4*)&Ks[r * FA_QS + dq] = *(const float4*)(k + base);
            *(float4*)&Vs[r * FA_QS + dq] = *(const float4*)(v + base);
        }
        __syncthreads();

        float s4[4][4];
        #pragma unroll
        for (int i = 0; i < 4; ++i)
            #pragma unroll
            for (int j = 0; j < 4; ++j) s4[i][j] = 0.f;

        #pragma unroll 8
        for (int kd = 0; kd < 128; kd += 4) {
            float4 qv[4], kv[4];
            #pragma unroll
            for (int i = 0; i < 4; ++i) qv[i] = *(const float4*)&Qs[(r0 + i) * FA_QS + kd];
            #pragma unroll
            for (int j = 0; j < 4; ++j) kv[j] = *(const float4*)&Ks[(tx + 16 * j) * FA_QS + kd];
            #pragma unroll
            for (int i = 0; i < 4; ++i)
                #pragma unroll
                for (int j = 0; j < 4; ++j) {
                    s4[i][j] = fmaf(qv[i].x, kv[j].x, s4[i][j]);
                    s4[i][j] = fmaf(qv[i].y, kv[j].y, s4[i][j]);
                    s4[i][j] = fmaf(qv[i].z, kv[j].z, s4[i][j]);
                    s4[i][j] = fmaf(qv[i].w, kv[j].w, s4[i][j]);
                }
        }

        #pragma unroll
        for (int i = 0; i < 4; ++i)
            #pragma unroll
            for (int j = 0; j < 4; ++j) {
                int gm = m0 + r0 + i;
                int gn = n0 + tx + 16 * j;
                Ps[(r0 + i) * FA_PS + tx + 16 * j] =
                    (gn <= gm) ? s4[i][j] * scale : -CUDART_INF_F;
            }
        __syncthreads();

        if (tid < 64) {
            const int r = tid;
            float mold = m_s[r];
            float rowm = -CUDART_INF_F;
            #pragma unroll 8
            for (int c = 0; c < 64; ++c) rowm = fmaxf(rowm, Ps[r * FA_PS + c]);
            float mnew = fmaxf(mold, rowm);
            float corr = expf(mold - mnew);
            float sum = 0.f;
            #pragma unroll 8
            for (int c = 0; c < 64; ++c) {
                float p = expf(Ps[r * FA_PS + c] - mnew);
                Ps[r * FA_PS + c] = p;
                sum += p;
            }
            l_s[r] = l_s[r] * corr + sum;
            m_s[r] = mnew;
            c_s[r] = corr;
        }
        __syncthreads();

        #pragma unroll
        for (int i = 0; i < 4; ++i) {
            float cf = c_s[r0 + i];
            #pragma unroll
            for (int j = 0; j < 8; ++j) acc[i][j] *= cf;
        }
        #pragma unroll 8
        for (int n = 0; n < 64; ++n) {
            float4 v0 = *(const float4*)&Vs[n * FA_QS + d0];
            float4 v1 = *(const float4*)&Vs[n * FA_QS + d0 + 4];
            #pragma unroll
            for (int i = 0; i < 4; ++i) {
                float p = Ps[(r0 + i) * FA_PS + n];
                acc[i][0] = fmaf(p, v0.x, acc[i][0]);
                acc[i][1] = fmaf(p, v0.y, acc[i][1]);
                acc[i][2] = fmaf(p, v0.z, acc[i][2]);
                acc[i][3] = fmaf(p, v0.w, acc[i][3]);
                acc[i][4] = fmaf(p, v1.x, acc[i][4]);
                acc[i][5] = fmaf(p, v1.y, acc[i][5]);
                acc[i][6] = fmaf(p, v1.z, acc[i][6]);
                acc[i][7] = fmaf(p, v1.w, acc[i][7]);
            }
        }
    }

    #pragma unroll
    for (int i = 0; i < 4; ++i) {
        float inv = 1.f / l_s[r0 + i];
        size_t off = ((size_t)((b * Sc + m0 + r0 + i) * NHc + h)) * HDc + d0;
        float4 o0 = make_float4(acc[i][0]*inv, acc[i][1]*inv, acc[i][2]*inv, acc[i][3]*inv);
        float4 o1 = make_float4(acc[i][4]*inv, acc[i][5]*inv, acc[i][6]*inv, acc[i][7]*inv);
        st_hilo4(oh, ol, off,     o0);
        st_hilo4(oh, ol, off + 4, o1);
    }
}

// ---------------------------------------------------------------------------
// SiLU(gate) * up -> bf16 hi/lo
// ---------------------------------------------------------------------------
__global__ __launch_bounds__(256)
void silu_mul_kernel(const float* __restrict__ gu,
                     __nv_bfloat16* __restrict__ ah, __nv_bfloat16* __restrict__ al)
{
    size_t idx = (size_t)blockIdx.x * blockDim.x + threadIdx.x;
    size_t m  = idx / (Ic / 4);
    size_t c4 = idx % (Ic / 4);
    const float4 g = *(const float4*)(gu + m * (size_t)(2 * Ic) + c4 * 4);
    const float4 u = *(const float4*)(gu + m * (size_t)(2 * Ic) + Ic + c4 * 4);
    float4 r;
    r.x = g.x / (1.f + expf(-g.x)) * u.x;
    r.y = g.y / (1.f + expf(-g.y)) * u.y;
    r.z = g.z / (1.f + expf(-g.z)) * u.z;
    r.w = g.w / (1.f + expf(-g.w)) * u.w;
    st_hilo4(ah, al, m * (size_t)Ic + c4 * 4, r);
}

// ---------------------------------------------------------------------------
// Launch
// ---------------------------------------------------------------------------
extern "C" void kernel_launch(void* const* d_in, const int* in_sizes, int n_in,
                              void* d_out, int out_size)
{
    const float* h_in  = (const float*)d_in[0];
    const float* sin_t = (const float*)d_in[1];
    const float* cos_t = (const float*)d_in[2];
    const float* w_ln1 = (const float*)d_in[3];
    const float* w_q   = (const float*)d_in[4];
    const float* w_k   = (const float*)d_in[5];
    const float* w_v   = (const float*)d_in[6];
    const float* w_o   = (const float*)d_in[7];
    const float* w_ln2 = (const float*)d_in[8];
    const float* w_gu  = (const float*)d_in[9];
    const float* w_dn  = (const float*)d_in[10];
    float* out = (float*)d_out;

    __nv_bfloat16 *p_lnh, *p_lnl, *p_ath, *p_atl, *p_ach, *p_acl;
    __nv_bfloat16 *p_wqh, *p_wql, *p_wkh, *p_wkl, *p_wvh, *p_wvl;
    __nv_bfloat16 *p_woh, *p_wol, *p_wguh, *p_wgul, *p_wdnh, *p_wdnl;
    float *p_q, *p_k, *p_v, *p_h1, *p_gu;
    cudaGetSymbolAddress((void**)&p_lnh, a_ln_h);   cudaGetSymbolAddress((void**)&p_lnl, a_ln_l);
    cudaGetSymbolAddress((void**)&p_ath, a_at_h);   cudaGetSymbolAddress((void**)&p_atl, a_at_l);
    cudaGetSymbolAddress((void**)&p_ach, a_ac_h);   cudaGetSymbolAddress((void**)&p_acl, a_ac_l);
    cudaGetSymbolAddress((void**)&p_wqh, wq_h);     cudaGetSymbolAddress((void**)&p_wql, wq_l);
    cudaGetSymbolAddress((void**)&p_wkh, wk_h);     cudaGetSymbolAddress((void**)&p_wkl, wk_l);
    cudaGetSymbolAddress((void**)&p_wvh, wv_h);     cudaGetSymbolAddress((void**)&p_wvl, wv_l);
    cudaGetSymbolAddress((void**)&p_woh, wo_h);     cudaGetSymbolAddress((void**)&p_wol, wo_l);
    cudaGetSymbolAddress((void**)&p_wguh, wgu_h);   cudaGetSymbolAddress((void**)&p_wgul, wgu_l);
    cudaGetSymbolAddress((void**)&p_wdnh, wdn_h);   cudaGetSymbolAddress((void**)&p_wdnl, wdn_l);
    cudaGetSymbolAddress((void**)&p_q,  g_q);
    cudaGetSymbolAddress((void**)&p_k,  g_k);
    cudaGetSymbolAddress((void**)&p_v,  g_v);
    cudaGetSymbolAddress((void**)&p_h1, g_h1);
    cudaGetSymbolAddress((void**)&p_gu, g_gu);

    cudaFuncSetAttribute(flash_attn_kernel,
                         cudaFuncAttributeMaxDynamicSharedMemorySize, FA_SMEM);
    cudaFuncSetAttribute(gemm_tc<false>,
                         cudaFuncAttributeMaxDynamicSharedMemorySize, GEMM_SMEM);
    cudaFuncSetAttribute(gemm_tc<true>,
                         cudaFuncAttributeMaxDynamicSharedMemorySize, GEMM_SMEM);

    // Weight splits (hi/lo bf16)
    cvt_hilo_kernel<<< (2048*2048/4)/256, 256>>>(w_q,  p_wqh,  p_wql,  2048*2048/4);
    cvt_hilo_kernel<<< ( 512*2048/4)/256, 256>>>(w_k,  p_wkh,  p_wkl,   512*2048/4);
    cvt_hilo_kernel<<< ( 512*2048/4)/256, 256>>>(w_v,  p_wvh,  p_wvl,   512*2048/4);
    cvt_hilo_kernel<<< (2048*2048/4)/256, 256>>>(w_o,  p_woh,  p_wol,  2048*2048/4);
    cvt_hilo_kernel<<<(16384*2048/4)/256, 256>>>(w_gu, p_wguh, p_wgul, 16384*2048/4);
    cvt_hilo_kernel<<< (2048*8192/4)/256, 256>>>(w_dn, p_wdnh, p_wdnl,  2048*8192/4);

    // 1. attn_in = rmsnorm(h) -> hi/lo
    rmsnorm_kernel<<<Mc, 256>>>(h_in, w_ln1, p_lnh, p_lnl);

    // 2. Q/K/V projections (mma.sync tensor cores)
    gemm_tc<false><<<dim3(2048/128, Mc/128), 256, GEMM_SMEM>>>(p_lnh, p_lnl, p_wqh, p_wql, nullptr, p_q, 2048, Hc);
    gemm_tc<false><<<dim3( 512/128, Mc/128), 256, GEMM_SMEM>>>(p_lnh, p_lnl, p_wkh, p_wkl, nullptr, p_k,  512, Hc);
    gemm_tc<false><<<dim3( 512/128, Mc/128), 256, GEMM_SMEM>>>(p_lnh, p_lnl, p_wvh, p_wvl, nullptr, p_v,  512, Hc);

    // 3. RoPE
    rope_kernel<<<(Mc*NHc*64  + 255)/256, 256>>>(p_q, sin_t, cos_t, NHc,  Mc*NHc*64);
    rope_kernel<<<(Mc*KVHc*64 + 255)/256, 256>>>(p_k, sin_t, cos_t, KVHc, Mc*KVHc*64);

    // 4. Flash attention -> hi/lo
    flash_attn_kernel<<<dim3(Sc/64, NHc, Bc), 256, FA_SMEM>>>(p_q, p_k, p_v, p_ath, p_atl);

    // 5. O projection + residual
    gemm_tc<true><<<dim3(2048/128, Mc/128), 256, GEMM_SMEM>>>(p_ath, p_atl, p_woh, p_wol, h_in, p_h1, 2048, 2048);

    // 6. mlp_in = rmsnorm(h1) -> hi/lo
    rmsnorm_kernel<<<Mc, 256>>>(p_h1, w_ln2, p_lnh, p_lnl);

    // 7. gate_up GEMM
    gemm_tc<false><<<dim3(16384/128, Mc/128), 256, GEMM_SMEM>>>(p_lnh, p_lnl, p_wguh, p_wgul, nullptr, p_gu, 16384, Hc);

    // 8. silu(gate)*up -> hi/lo
    silu_mul_kernel<<<(Mc*(Ic/4))/256, 256>>>(p_gu, p_ach, p_acl);

    // 9. down GEMM + residual -> out
    gemm_tc<true><<<dim3(2048/128, Mc/128), 256, GEMM_SMEM>>>(p_ach, p_acl, p_wdnh, p_wdnl, p_h1, out, 2048, Ic);
}